// round 13
// baseline (speedup 1.0000x reference)
#include <cuda_runtime.h>
#include <cuda_bf16.h>
#include <cstdint>

// ---------------- problem constants ----------------
constexpr int T_   = 256;
constexpr int B_   = 2048;
constexpr long long TB_ = (long long)T_ * B_;   // 524288

// ---------------- device scratch ----------------
__device__ __nv_bfloat16 g_Abf[(size_t)TB_ * 128];   // gate preacts bf16 (128 MiB)
__device__ __nv_bfloat16 g_W1b[128 * 512];
__device__ __nv_bfloat16 g_W2b[128 * 128];
__device__ __nv_bfloat16 g_Mb [128 * 128];           // fused Wih@W3 in bf16
__device__ float g_bAv[128];                         // fused bias Wih@b3 + bih + bhh

// ---------------- fast math ----------------
__device__ __forceinline__ float fast_tanh(float x) {
    float y;
    asm("tanh.approx.f32 %0, %1;" : "=f"(y) : "f"(x));
    return y;
}
__device__ __forceinline__ float fast_sig(float x) {
    return 0.5f + 0.5f * fast_tanh(0.5f * x);
}
__device__ __forceinline__ uint32_t packbf(float a, float b) {
    __nv_bfloat162 h = __float22bfloat162_rn(make_float2(a, b));
    return *(uint32_t*)&h;
}

// ---------------- prep: parallel M = Wih @ W3, conversions ----------------
__global__ void prep_kernel(const float* __restrict__ W1,
                            const float* __restrict__ W2,
                            const float* __restrict__ Wih,
                            const float* __restrict__ W3,
                            const float* __restrict__ b3,
                            const float* __restrict__ bih,
                            const float* __restrict__ bhh)
{
    const int bx = blockIdx.x, tid = threadIdx.x;
    if (bx < 8) {
        __shared__ float sW3[64 * 128];
        for (int i = tid; i < 64 * 128; i += 256) sW3[i] = W3[i];
        __syncthreads();
        const int g  = bx * 16 + (tid >> 4);
        const int c0 = (tid & 15) * 8;
        float a[64];
        #pragma unroll
        for (int d = 0; d < 64; d++) a[d] = Wih[g * 64 + d];
        float acc[8];
        #pragma unroll
        for (int q = 0; q < 8; q++) acc[q] = 0.f;
        #pragma unroll 8
        for (int d = 0; d < 64; d++) {
            const float av = a[d];
            const float* w = &sW3[d * 128 + c0];
            #pragma unroll
            for (int q = 0; q < 8; q++) acc[q] = fmaf(av, w[q], acc[q]);
        }
        #pragma unroll
        for (int q = 0; q < 8; q++) g_Mb[g * 128 + c0 + q] = __float2bfloat16(acc[q]);

        if (bx == 0 && tid < 128) {
            float s = bih[tid] + bhh[tid];
            #pragma unroll 16
            for (int d = 0; d < 64; d++) s += Wih[tid * 64 + d] * b3[d];
            g_bAv[tid] = s;
        }
    } else {
        const int start = (bx - 8) * 256 + tid;
        const int stride = 40 * 256;
        for (int i = start; i < 128 * 512 + 128 * 128; i += stride) {
            if (i < 128 * 512) g_W1b[i] = __float2bfloat16(W1[i]);
            else               g_W2b[i - 128 * 512] = __float2bfloat16(W2[i - 128 * 512]);
        }
    }
}

// ---------------- MMA primitives (legacy mma.sync — tcgen05 rejected by sm_103 ptxas) ----------------
__device__ __forceinline__ void ldsm_x4(uint32_t addr, uint32_t& r0, uint32_t& r1,
                                        uint32_t& r2, uint32_t& r3) {
    asm volatile("ldmatrix.sync.aligned.m8n8.x4.shared.b16 {%0,%1,%2,%3}, [%4];"
                 : "=r"(r0), "=r"(r1), "=r"(r2), "=r"(r3) : "r"(addr));
}
__device__ __forceinline__ void mma16816(float* c, uint32_t a0, uint32_t a1, uint32_t a2,
                                         uint32_t a3, uint32_t b0, uint32_t b1) {
    asm volatile("mma.sync.aligned.m16n8k16.row.col.f32.bf16.bf16.f32 "
                 "{%0,%1,%2,%3},{%4,%5,%6,%7},{%8,%9},{%0,%1,%2,%3};"
                 : "+f"(c[0]), "+f"(c[1]), "+f"(c[2]), "+f"(c[3])
                 : "r"(a0), "r"(a1), "r"(a2), "r"(a3), "r"(b0), "r"(b1));
}

// one 16-wide k-step of the 128x128 block tile; both operands K-major in smem
__device__ __forceinline__ void mma_tile(uint32_t sbase, int aOff, int aStride,
                                         int bOff, int bStride,
                                         int wm, int wn, int lane,
                                         float (&acc)[4][4][4])
{
    uint32_t b[4][2];
    const int brow0 = wn * 32 + ((lane >> 4) << 3) + (lane & 7);
    const int bko   = ((lane >> 3) & 1) * 16;
    #pragma unroll
    for (int t = 0; t < 2; t++) {
        uint32_t addr = sbase + (uint32_t)(bOff + (brow0 + t * 16) * bStride + bko);
        uint32_t r0, r1, r2, r3;
        ldsm_x4(addr, r0, r1, r2, r3);
        b[t * 2][0] = r0; b[t * 2][1] = r1;
        b[t * 2 + 1][0] = r2; b[t * 2 + 1][1] = r3;
    }
    const int arow0 = wm * 64 + (lane & 15);
    const int ako   = (lane >> 4) * 16;
    #pragma unroll
    for (int i = 0; i < 4; i++) {
        uint32_t addr = sbase + (uint32_t)(aOff + (arow0 + i * 16) * aStride + ako);
        uint32_t a0, a1, a2, a3;
        ldsm_x4(addr, a0, a1, a2, a3);
        #pragma unroll
        for (int j = 0; j < 4; j++)
            mma16816(acc[i][j], a0, a1, a2, a3, b[j][0], b[j][1]);
    }
}

// ---------------- fused 3-stage encoder (R7 mainloop; W2+M co-resident) ----------------
// smem layout (bytes):
//   [0, 34816)         Zsm: 128 x 136 bf16 (stride 272B)
//   [34816, 104448)    union: stage1 { Asm[2][128][24] @+0, Wsm[2][128][24] @+12288 }
//                      then W2 tile @+0 (128x272B) and M tile @+34816 (128x272B)
//   [104448, 105984)   b1s, b2s, bAs
constexpr int Z_OFF   = 0;
constexpr int U_OFF   = 34816;
constexpr int A1_OFF  = U_OFF;            // stage1 A buffers (6144B each)
constexpr int W1_OFF  = U_OFF + 12288;    // stage1 W buffers
constexpr int W2_OFF  = U_OFF;            // stage2 weights (272B rows)
constexpr int M2_OFF  = U_OFF + 34816;    // stage3 weights (272B rows), loaded once
constexpr int BIAS_OFF= 104448;
constexpr int SMEM_BYTES = 105984;        // 2 blocks/SM: 211,968B <= 228KB carveout

__global__ __launch_bounds__(256, 2)
void encoder(const float* __restrict__ x,
             const float* __restrict__ b1,
             const float* __restrict__ b2)
{
    extern __shared__ char smem[];
    const uint32_t sbase = (uint32_t)__cvta_generic_to_shared(smem);

    const int tid  = threadIdx.x;
    const int lane = tid & 31;
    const int warp = tid >> 5;
    const int wm = warp >> 2;       // 0..1
    const int wn = warp & 3;        // 0..3
    const size_t m0 = (size_t)blockIdx.x * 128;

    float* b1s = (float*)(smem + BIAS_OFF);
    float* b2s = b1s + 128;
    float* bAs = b2s + 128;
    if (tid < 128) { b1s[tid] = b1[tid]; b2s[tid] = b2[tid]; bAs[tid] = g_bAv[tid]; }

    float acc[4][4][4];
    #pragma unroll
    for (int i = 0; i < 4; i++)
        #pragma unroll
        for (int j = 0; j < 4; j++)
            #pragma unroll
            for (int r = 0; r < 4; r++) acc[i][j][r] = 0.f;

    // ================= stage 1: z1 = tanh(x @ W1^T + b1), K=512 =================
    const int lrow  = tid >> 1;
    const int lhalf = tid & 1;
    const float* Ap = x + (m0 + (size_t)lrow) * 512 + lhalf * 8;
    const __nv_bfloat16* Wp = g_W1b + lrow * 512 + lhalf * 8;
    const int sAoff = A1_OFF + lrow * 48 + lhalf * 16;
    const int sWoff = W1_OFF + lrow * 48 + lhalf * 16;

    { // prologue: tile 0
        float4 f0 = *(const float4*)(Ap);
        float4 f1 = *(const float4*)(Ap + 4);
        uint4  wv = *(const uint4*)(Wp);
        uint4  av;
        av.x = packbf(f0.x, f0.y); av.y = packbf(f0.z, f0.w);
        av.z = packbf(f1.x, f1.y); av.w = packbf(f1.z, f1.w);
        *(uint4*)(smem + sAoff) = av;
        *(uint4*)(smem + sWoff) = wv;
    }
    __syncthreads();

    #pragma unroll 2
    for (int ks = 0; ks < 32; ks++) {
        const int cur = ks & 1;
        uint4 av, wv;
        const bool has = ks < 31;
        if (has) {
            const float* ap = Ap + (ks + 1) * 16;
            float4 f0 = *(const float4*)(ap);
            float4 f1 = *(const float4*)(ap + 4);
            wv = *(const uint4*)(Wp + (ks + 1) * 16);
            av.x = packbf(f0.x, f0.y); av.y = packbf(f0.z, f0.w);
            av.z = packbf(f1.x, f1.y); av.w = packbf(f1.z, f1.w);
        }
        mma_tile(sbase, A1_OFF + cur * 6144, 48, W1_OFF + cur * 6144, 48,
                 wm, wn, lane, acc);
        if (has) {
            const int nxt = cur ^ 1;
            *(uint4*)(smem + sAoff + nxt * 6144) = av;
            *(uint4*)(smem + sWoff + nxt * 6144) = wv;
        }
        __syncthreads();
    }

    // epilogue 1 -> Zsm (bf16)
    #pragma unroll
    for (int i = 0; i < 4; i++) {
        #pragma unroll
        for (int j = 0; j < 4; j++) {
            const int row = wm * 64 + i * 16 + (lane >> 2);
            const int col = wn * 32 + j * 8 + (lane & 3) * 2;
            const float bb0 = b1s[col], bb1 = b1s[col + 1];
            float* c = acc[i][j];
            *(uint32_t*)(smem + Z_OFF + row * 272 + col * 2) =
                packbf(fast_tanh(c[0] + bb0), fast_tanh(c[1] + bb1));
            *(uint32_t*)(smem + Z_OFF + (row + 8) * 272 + col * 2) =
                packbf(fast_tanh(c[2] + bb0), fast_tanh(c[3] + bb1));
            c[0] = c[1] = c[2] = c[3] = 0.f;
        }
    }

    // combined W2 + M load into the freed union region (single phase, one sync)
    for (int idx = tid; idx < 2048; idx += 256) {
        const int row = idx >> 4, c = idx & 15;
        *(uint4*)(smem + W2_OFF + row * 272 + c * 16) =
            *(const uint4*)(g_W2b + row * 128 + c * 8);
        *(uint4*)(smem + M2_OFF + row * 272 + c * 16) =
            *(const uint4*)(g_Mb + row * 128 + c * 8);
    }
    __syncthreads();

    // ================= stage 2: z2 = tanh(z1 @ W2^T + b2), K=128 =================
    #pragma unroll
    for (int ks = 0; ks < 8; ks++)
        mma_tile(sbase, Z_OFF + ks * 32, 272, W2_OFF + ks * 32, 272, wm, wn, lane, acc);
    __syncthreads();   // all reads of Zsm done before overwrite

    #pragma unroll
    for (int i = 0; i < 4; i++) {
        #pragma unroll
        for (int j = 0; j < 4; j++) {
            const int row = wm * 64 + i * 16 + (lane >> 2);
            const int col = wn * 32 + j * 8 + (lane & 3) * 2;
            const float bb0 = b2s[col], bb1 = b2s[col + 1];
            float* c = acc[i][j];
            *(uint32_t*)(smem + Z_OFF + row * 272 + col * 2) =
                packbf(fast_tanh(c[0] + bb0), fast_tanh(c[1] + bb1));
            *(uint32_t*)(smem + Z_OFF + (row + 8) * 272 + col * 2) =
                packbf(fast_tanh(c[2] + bb0), fast_tanh(c[3] + bb1));
            c[0] = c[1] = c[2] = c[3] = 0.f;
        }
    }
    __syncthreads();

    // ================= stage 3: A = z2 @ M^T + bA, K=128, bf16 out (M resident) =================
    #pragma unroll
    for (int ks = 0; ks < 8; ks++)
        mma_tile(sbase, Z_OFF + ks * 32, 272, M2_OFF + ks * 32, 272, wm, wn, lane, acc);

    #pragma unroll
    for (int i = 0; i < 4; i++) {
        #pragma unroll
        for (int j = 0; j < 4; j++) {
            const int row = wm * 64 + i * 16 + (lane >> 2);
            const int col = wn * 32 + j * 8 + (lane & 3) * 2;
            const float bb0 = bAs[col], bb1 = bAs[col + 1];
            float* c = acc[i][j];
            *(uint32_t*)(g_Abf + (m0 + row) * 128 + col)     = packbf(c[0] + bb0, c[1] + bb1);
            *(uint32_t*)(g_Abf + (m0 + row + 8) * 128 + col) = packbf(c[2] + bb0, c[3] + bb1);
        }
    }
}

// ---------------- softmax/emit (no-max: |logits| << 1, exp range safe; validated R10/R12) ----------------
__device__ __forceinline__ void emit_out(int tout, int b, int lane,
    float lp, float blogv,
    const int* __restrict__ action,
    float* __restrict__ out_act, float* __restrict__ out_lp, float* __restrict__ out_ent)
{
    const unsigned FULL = 0xffffffffu;
    float l = lp + blogv;            // lanes >=16 carry 0; isolated by width-16 shuffles
    float e = __expf(l);
    float s = e, el = e * l;
    #pragma unroll
    for (int k = 8; k > 0; k >>= 1) {
        s  += __shfl_xor_sync(FULL, s,  k, 16);
        el += __shfl_xor_sync(FULL, el, k, 16);
    }
    float logZ = __logf(s);
    float ent  = logZ - el / s;      // H = logZ - sum(p * l)
    size_t idx = (size_t)tout * B_ + b;
    int a = action[idx];
    float lpa = __shfl_sync(FULL, l, a, 16) - logZ;
    if (lane == 0) {
        out_act[idx] = (float)a;
        out_lp[idx]  = lpa;
        out_ent[idx] = ent;
    }
}

// ---------------- LSTM recurrence + head, 2 batch elems per warp (R7 structure, no prefetch) ----------------
__global__ __launch_bounds__(128)
void lstm_head(const __nv_bfloat16* __restrict__ A,   // [T,B,128] bf16 gate preacts
               const int*   __restrict__ done,
               const int*   __restrict__ action,
               const float* __restrict__ Whh,          // [128,32]
               const float* __restrict__ Wlog,         // [16,32]
               const float* __restrict__ blog,         // [16]
               const float* __restrict__ h0,
               const float* __restrict__ c0,
               float* __restrict__ out)                // [3,T,B]
{
    __shared__ float WlogT[32][32];
    const int tid = threadIdx.x;
    for (int idx = tid; idx < 1024; idx += 128) {
        int j = idx >> 5, a = idx & 31;
        WlogT[j][a] = (a < 16) ? Wlog[a * 32 + j] : 0.f;
    }
    __syncthreads();

    const int lane = tid & 31;
    const int warp = (blockIdx.x * 128 + tid) >> 5;   // 0..1023
    const int b0 = warp * 2;
    const int b1 = b0 + 1;

    float wi[32], wf[32], wg[32], wo[32];
    #pragma unroll
    for (int j = 0; j < 32; j++) {
        wi[j] = Whh[(     lane) * 32 + j];
        wf[j] = Whh[(32 + lane) * 32 + j];
        wg[j] = Whh[(64 + lane) * 32 + j];
        wo[j] = Whh[(96 + lane) * 32 + j];
    }
    float blogv = (lane < 16) ? blog[lane] : 0.f;

    float hr0 = h0[b0 * 32 + lane], cr0 = c0[b0 * 32 + lane];
    float hr1 = h0[b1 * 32 + lane], cr1 = c0[b1 * 32 + lane];

    float* out_act = out;
    float* out_lp  = out + (size_t)TB_;
    float* out_ent = out + (size_t)2 * TB_;

    const unsigned FULL = 0xffffffffu;

    for (int t = 0; t < T_; t++) {
        const float m0 = 1.f - (float)done[t * B_ + b0];
        const float m1 = 1.f - (float)done[t * B_ + b1];
        const __nv_bfloat16* A0 = A + ((size_t)t * B_ + b0) * 128;
        const __nv_bfloat16* A1 = A0 + 128;
        const float ai0 = __bfloat162float(A0[lane]);
        const float af0 = __bfloat162float(A0[32 + lane]);
        const float ag0 = __bfloat162float(A0[64 + lane]);
        const float ao0 = __bfloat162float(A0[96 + lane]);
        const float ai1 = __bfloat162float(A1[lane]);
        const float af1 = __bfloat162float(A1[32 + lane]);
        const float ag1 = __bfloat162float(A1[64 + lane]);
        const float ao1 = __bfloat162float(A1[96 + lane]);

        float gi0 = 0, gf0 = 0, gg0 = 0, go0 = 0, lp0 = 0;
        float gi1 = 0, gf1 = 0, gg1 = 0, go1 = 0, lp1 = 0;
        #pragma unroll
        for (int j = 0; j < 32; j++) {
            const float hv0 = __shfl_sync(FULL, hr0, j);
            const float hv1 = __shfl_sync(FULL, hr1, j);
            const float wl  = WlogT[j][lane];
            gi0 = fmaf(hv0, wi[j], gi0);  gi1 = fmaf(hv1, wi[j], gi1);
            gf0 = fmaf(hv0, wf[j], gf0);  gf1 = fmaf(hv1, wf[j], gf1);
            gg0 = fmaf(hv0, wg[j], gg0);  gg1 = fmaf(hv1, wg[j], gg1);
            go0 = fmaf(hv0, wo[j], go0);  go1 = fmaf(hv1, wo[j], go1);
            lp0 = fmaf(hv0, wl,    lp0);  lp1 = fmaf(hv1, wl,    lp1);
        }

        if (t > 0) {
            emit_out(t - 1, b0, lane, lp0, blogv, action, out_act, out_lp, out_ent);
            emit_out(t - 1, b1, lane, lp1, blogv, action, out_act, out_lp, out_ent);
        }

        float ig = fast_sig (fmaf(m0, gi0, ai0));
        float fg = fast_sig (fmaf(m0, gf0, af0));
        float gv = fast_tanh(fmaf(m0, gg0, ag0));
        float og = fast_sig (fmaf(m0, go0, ao0));
        cr0 = fg * (m0 * cr0) + ig * gv;
        hr0 = og * fast_tanh(cr0);

        ig = fast_sig (fmaf(m1, gi1, ai1));
        fg = fast_sig (fmaf(m1, gf1, af1));
        gv = fast_tanh(fmaf(m1, gg1, ag1));
        og = fast_sig (fmaf(m1, go1, ao1));
        cr1 = fg * (m1 * cr1) + ig * gv;
        hr1 = og * fast_tanh(cr1);
    }

    float lp0 = 0, lp1 = 0;
    #pragma unroll
    for (int j = 0; j < 32; j++) {
        const float hv0 = __shfl_sync(FULL, hr0, j);
        const float hv1 = __shfl_sync(FULL, hr1, j);
        const float wl  = WlogT[j][lane];
        lp0 = fmaf(hv0, wl, lp0);
        lp1 = fmaf(hv1, wl, lp1);
    }
    emit_out(T_ - 1, b0, lane, lp0, blogv, action, out_act, out_lp, out_ent);
    emit_out(T_ - 1, b1, lane, lp1, blogv, action, out_act, out_lp, out_ent);
}

// ---------------- launcher ----------------
extern "C" void kernel_launch(void* const* d_in, const int* in_sizes, int n_in,
                              void* d_out, int out_size)
{
    (void)in_sizes; (void)n_in; (void)out_size;
    const float* x     = (const float*)d_in[0];
    const int*   done  = (const int*)  d_in[1];
    const int*   action= (const int*)  d_in[2];
    const float* W1    = (const float*)d_in[3];
    const float* b1    = (const float*)d_in[4];
    const float* W2    = (const float*)d_in[5];
    const float* b2    = (const float*)d_in[6];
    const float* W3    = (const float*)d_in[7];
    const float* b3    = (const float*)d_in[8];
    const float* Wih   = (const float*)d_in[9];
    const float* Whh   = (const float*)d_in[10];
    const float* bih   = (const float*)d_in[11];
    const float* bhh   = (const float*)d_in[12];
    const float* Wlog  = (const float*)d_in[13];
    const float* blog  = (const float*)d_in[14];
    const float* h0    = (const float*)d_in[15];
    const float* c0    = (const float*)d_in[16];
    float* out = (float*)d_out;

    void* pA;
    cudaGetSymbolAddress(&pA, g_Abf);
    const __nv_bfloat16* Abuf = (const __nv_bfloat16*)pA;

    cudaFuncSetAttribute(encoder, cudaFuncAttributeMaxDynamicSharedMemorySize, SMEM_BYTES);

    prep_kernel<<<48, 256>>>(W1, W2, Wih, W3, b3, bih, bhh);
    encoder<<<(int)(TB_ / 128), 256, SMEM_BYTES>>>(x, b1, b2);
    lstm_head<<<B_ / 8, 128>>>(Abuf, done, action, Whh, Wlog, blog, h0, c0, out);  // 2 elems/warp, 1 wave
}

// round 14
// speedup vs baseline: 1.0474x; 1.0474x over previous
#include <cuda_runtime.h>
#include <cuda_bf16.h>
#include <cstdint>

// ---------------- problem constants ----------------
constexpr int T_   = 256;
constexpr int B_   = 2048;
constexpr long long TB_ = (long long)T_ * B_;   // 524288

// ---------------- device scratch ----------------
__device__ __nv_bfloat16 g_Abf[(size_t)TB_ * 128];   // gate preacts bf16 (128 MiB)
__device__ __nv_bfloat16 g_W1b[128 * 512];
__device__ __nv_bfloat16 g_W2b[128 * 128];
__device__ __nv_bfloat16 g_Mb [128 * 128];           // fused Wih@W3 in bf16
__device__ float g_bAv[128];                         // fused bias Wih@b3 + bih + bhh

// ---------------- fast math ----------------
__device__ __forceinline__ float fast_tanh(float x) {
    float y;
    asm("tanh.approx.f32 %0, %1;" : "=f"(y) : "f"(x));
    return y;
}
__device__ __forceinline__ float fast_sig(float x) {
    return 0.5f + 0.5f * fast_tanh(0.5f * x);
}
__device__ __forceinline__ uint32_t packbf(float a, float b) {
    __nv_bfloat162 h = __float22bfloat162_rn(make_float2(a, b));
    return *(uint32_t*)&h;
}

// ---------------- prep: parallel M = Wih @ W3, conversions ----------------
__global__ void prep_kernel(const float* __restrict__ W1,
                            const float* __restrict__ W2,
                            const float* __restrict__ Wih,
                            const float* __restrict__ W3,
                            const float* __restrict__ b3,
                            const float* __restrict__ bih,
                            const float* __restrict__ bhh)
{
    const int bx = blockIdx.x, tid = threadIdx.x;
    if (bx < 8) {
        __shared__ float sW3[64 * 128];
        for (int i = tid; i < 64 * 128; i += 256) sW3[i] = W3[i];
        __syncthreads();
        const int g  = bx * 16 + (tid >> 4);
        const int c0 = (tid & 15) * 8;
        float a[64];
        #pragma unroll
        for (int d = 0; d < 64; d++) a[d] = Wih[g * 64 + d];
        float acc[8];
        #pragma unroll
        for (int q = 0; q < 8; q++) acc[q] = 0.f;
        #pragma unroll 8
        for (int d = 0; d < 64; d++) {
            const float av = a[d];
            const float* w = &sW3[d * 128 + c0];
            #pragma unroll
            for (int q = 0; q < 8; q++) acc[q] = fmaf(av, w[q], acc[q]);
        }
        #pragma unroll
        for (int q = 0; q < 8; q++) g_Mb[g * 128 + c0 + q] = __float2bfloat16(acc[q]);

        if (bx == 0 && tid < 128) {
            float s = bih[tid] + bhh[tid];
            #pragma unroll 16
            for (int d = 0; d < 64; d++) s += Wih[tid * 64 + d] * b3[d];
            g_bAv[tid] = s;
        }
    } else {
        const int start = (bx - 8) * 256 + tid;
        const int stride = 40 * 256;
        for (int i = start; i < 128 * 512 + 128 * 128; i += stride) {
            if (i < 128 * 512) g_W1b[i] = __float2bfloat16(W1[i]);
            else               g_W2b[i - 128 * 512] = __float2bfloat16(W2[i - 128 * 512]);
        }
    }
}

// ---------------- MMA primitives (legacy mma.sync — tcgen05 rejected by sm_103 ptxas) ----------------
__device__ __forceinline__ void ldsm_x4(uint32_t addr, uint32_t& r0, uint32_t& r1,
                                        uint32_t& r2, uint32_t& r3) {
    asm volatile("ldmatrix.sync.aligned.m8n8.x4.shared.b16 {%0,%1,%2,%3}, [%4];"
                 : "=r"(r0), "=r"(r1), "=r"(r2), "=r"(r3) : "r"(addr));
}
__device__ __forceinline__ void mma16816(float* c, uint32_t a0, uint32_t a1, uint32_t a2,
                                         uint32_t a3, uint32_t b0, uint32_t b1) {
    asm volatile("mma.sync.aligned.m16n8k16.row.col.f32.bf16.bf16.f32 "
                 "{%0,%1,%2,%3},{%4,%5,%6,%7},{%8,%9},{%0,%1,%2,%3};"
                 : "+f"(c[0]), "+f"(c[1]), "+f"(c[2]), "+f"(c[3])
                 : "r"(a0), "r"(a1), "r"(a2), "r"(a3), "r"(b0), "r"(b1));
}

// one 16-wide k-step of the 128x128 block tile; both operands K-major in smem
__device__ __forceinline__ void mma_tile(uint32_t sbase, int aOff, int aStride,
                                         int bOff, int bStride,
                                         int wm, int wn, int lane,
                                         float (&acc)[4][4][4])
{
    uint32_t b[4][2];
    const int brow0 = wn * 32 + ((lane >> 4) << 3) + (lane & 7);
    const int bko   = ((lane >> 3) & 1) * 16;
    #pragma unroll
    for (int t = 0; t < 2; t++) {
        uint32_t addr = sbase + (uint32_t)(bOff + (brow0 + t * 16) * bStride + bko);
        uint32_t r0, r1, r2, r3;
        ldsm_x4(addr, r0, r1, r2, r3);
        b[t * 2][0] = r0; b[t * 2][1] = r1;
        b[t * 2 + 1][0] = r2; b[t * 2 + 1][1] = r3;
    }
    const int arow0 = wm * 64 + (lane & 15);
    const int ako   = (lane >> 4) * 16;
    #pragma unroll
    for (int i = 0; i < 4; i++) {
        uint32_t addr = sbase + (uint32_t)(aOff + (arow0 + i * 16) * aStride + ako);
        uint32_t a0, a1, a2, a3;
        ldsm_x4(addr, a0, a1, a2, a3);
        #pragma unroll
        for (int j = 0; j < 4; j++)
            mma16816(acc[i][j], a0, a1, a2, a3, b[j][0], b[j][1]);
    }
}

// ---------------- fused 3-stage encoder (R3-proven structure, bf16 output) ----------------
// smem layout (bytes):
//   [0, 34816)        Zsm: 128 x 136 bf16 (stride 272B) — stage intermediates
//   [34816, 69632)    union: stage1 { Asm[2][128][24], Wsm[2][128][24] } / Wbig 128x136 bf16
//   [69632, 71168)    b1s, b2s, bAs (128 fp32 each)
constexpr int Z_OFF   = 0;
constexpr int U_OFF   = 34816;
constexpr int A1_OFF  = U_OFF;            // stage1 A buffers (6144B each)
constexpr int W1_OFF  = U_OFF + 12288;    // stage1 W buffers
constexpr int WB_OFF  = U_OFF;            // stage2/3 resident weights (stride 272B)
constexpr int BIAS_OFF= 69632;
constexpr int SMEM_BYTES = 71168;

__global__ __launch_bounds__(256, 2)
void encoder(const float* __restrict__ x,
             const float* __restrict__ b1,
             const float* __restrict__ b2)
{
    extern __shared__ char smem[];
    const uint32_t sbase = (uint32_t)__cvta_generic_to_shared(smem);

    const int tid  = threadIdx.x;
    const int lane = tid & 31;
    const int warp = tid >> 5;
    const int wm = warp >> 2;       // 0..1
    const int wn = warp & 3;        // 0..3
    const size_t m0 = (size_t)blockIdx.x * 128;

    float* b1s = (float*)(smem + BIAS_OFF);
    float* b2s = b1s + 128;
    float* bAs = b2s + 128;
    if (tid < 128) { b1s[tid] = b1[tid]; b2s[tid] = b2[tid]; bAs[tid] = g_bAv[tid]; }

    float acc[4][4][4];
    #pragma unroll
    for (int i = 0; i < 4; i++)
        #pragma unroll
        for (int j = 0; j < 4; j++)
            #pragma unroll
            for (int r = 0; r < 4; r++) acc[i][j][r] = 0.f;

    // ================= stage 1: z1 = tanh(x @ W1^T + b1), K=512 =================
    const int lrow  = tid >> 1;
    const int lhalf = tid & 1;
    const float* Ap = x + (m0 + (size_t)lrow) * 512 + lhalf * 8;
    const __nv_bfloat16* Wp = g_W1b + lrow * 512 + lhalf * 8;
    const int sAoff = A1_OFF + lrow * 48 + lhalf * 16;   // byte offsets within smem
    const int sWoff = W1_OFF + lrow * 48 + lhalf * 16;

    { // prologue: tile 0
        float4 f0 = *(const float4*)(Ap);
        float4 f1 = *(const float4*)(Ap + 4);
        uint4  wv = *(const uint4*)(Wp);
        uint4  av;
        av.x = packbf(f0.x, f0.y); av.y = packbf(f0.z, f0.w);
        av.z = packbf(f1.x, f1.y); av.w = packbf(f1.z, f1.w);
        *(uint4*)(smem + sAoff) = av;
        *(uint4*)(smem + sWoff) = wv;
    }
    __syncthreads();

    #pragma unroll 2
    for (int ks = 0; ks < 32; ks++) {
        const int cur = ks & 1;
        uint4 av, wv;
        const bool has = ks < 31;
        if (has) {
            const float* ap = Ap + (ks + 1) * 16;
            float4 f0 = *(const float4*)(ap);
            float4 f1 = *(const float4*)(ap + 4);
            wv = *(const uint4*)(Wp + (ks + 1) * 16);
            av.x = packbf(f0.x, f0.y); av.y = packbf(f0.z, f0.w);
            av.z = packbf(f1.x, f1.y); av.w = packbf(f1.z, f1.w);
        }
        mma_tile(sbase, A1_OFF + cur * 6144, 48, W1_OFF + cur * 6144, 48,
                 wm, wn, lane, acc);
        if (has) {
            const int nxt = cur ^ 1;
            *(uint4*)(smem + sAoff + nxt * 6144) = av;
            *(uint4*)(smem + sWoff + nxt * 6144) = wv;
        }
        __syncthreads();
    }

    // epilogue 1 -> Zsm (bf16)
    #pragma unroll
    for (int i = 0; i < 4; i++) {
        #pragma unroll
        for (int j = 0; j < 4; j++) {
            const int row = wm * 64 + i * 16 + (lane >> 2);
            const int col = wn * 32 + j * 8 + (lane & 3) * 2;
            const float bb0 = b1s[col], bb1 = b1s[col + 1];
            float* c = acc[i][j];
            *(uint32_t*)(smem + Z_OFF + row * 272 + col * 2) =
                packbf(fast_tanh(c[0] + bb0), fast_tanh(c[1] + bb1));
            *(uint32_t*)(smem + Z_OFF + (row + 8) * 272 + col * 2) =
                packbf(fast_tanh(c[2] + bb0), fast_tanh(c[3] + bb1));
            c[0] = c[1] = c[2] = c[3] = 0.f;
        }
    }
    __syncthreads();

    // ================= stage 2: z2 = tanh(z1 @ W2^T + b2), K=128 =================
    for (int idx = tid; idx < 2048; idx += 256) {   // load W2 -> Wbig (32KB)
        const int row = idx >> 4, c = idx & 15;
        *(uint4*)(smem + WB_OFF + row * 272 + c * 16) =
            *(const uint4*)(g_W2b + row * 128 + c * 8);
    }
    __syncthreads();

    #pragma unroll
    for (int ks = 0; ks < 8; ks++)
        mma_tile(sbase, Z_OFF + ks * 32, 272, WB_OFF + ks * 32, 272, wm, wn, lane, acc);
    __syncthreads();   // all reads of Zsm done before overwrite

    #pragma unroll
    for (int i = 0; i < 4; i++) {
        #pragma unroll
        for (int j = 0; j < 4; j++) {
            const int row = wm * 64 + i * 16 + (lane >> 2);
            const int col = wn * 32 + j * 8 + (lane & 3) * 2;
            const float bb0 = b2s[col], bb1 = b2s[col + 1];
            float* c = acc[i][j];
            *(uint32_t*)(smem + Z_OFF + row * 272 + col * 2) =
                packbf(fast_tanh(c[0] + bb0), fast_tanh(c[1] + bb1));
            *(uint32_t*)(smem + Z_OFF + (row + 8) * 272 + col * 2) =
                packbf(fast_tanh(c[2] + bb0), fast_tanh(c[3] + bb1));
            c[0] = c[1] = c[2] = c[3] = 0.f;
        }
    }
    __syncthreads();

    // ================= stage 3: A = z2 @ M^T + bA, K=128, bf16 out =================
    for (int idx = tid; idx < 2048; idx += 256) {   // load M -> Wbig
        const int row = idx >> 4, c = idx & 15;
        *(uint4*)(smem + WB_OFF + row * 272 + c * 16) =
            *(const uint4*)(g_Mb + row * 128 + c * 8);
    }
    __syncthreads();

    #pragma unroll
    for (int ks = 0; ks < 8; ks++)
        mma_tile(sbase, Z_OFF + ks * 32, 272, WB_OFF + ks * 32, 272, wm, wn, lane, acc);

    #pragma unroll
    for (int i = 0; i < 4; i++) {
        #pragma unroll
        for (int j = 0; j < 4; j++) {
            const int row = wm * 64 + i * 16 + (lane >> 2);
            const int col = wn * 32 + j * 8 + (lane & 3) * 2;
            const float bb0 = bAs[col], bb1 = bAs[col + 1];
            float* c = acc[i][j];
            *(uint32_t*)(g_Abf + (m0 + row) * 128 + col)     = packbf(c[0] + bb0, c[1] + bb1);
            *(uint32_t*)(g_Abf + (m0 + row + 8) * 128 + col) = packbf(c[2] + bb0, c[3] + bb1);
        }
    }
}

// ---------------- softmax/emit helper (lanes 0..15 hold logits) ----------------
__device__ __forceinline__ void emit_out(int tout, int b, int lane,
    float lp, float blogv,
    const int* __restrict__ action,
    float* __restrict__ out_act, float* __restrict__ out_lp, float* __restrict__ out_ent)
{
    const unsigned FULL = 0xffffffffu;
    float l = lp + blogv;
    float mx = l;
    #pragma unroll
    for (int k = 8; k > 0; k >>= 1)
        mx = fmaxf(mx, __shfl_xor_sync(FULL, mx, k, 16));
    float e = __expf(l - mx);
    float s = e, el = e * l;
    #pragma unroll
    for (int k = 8; k > 0; k >>= 1) {
        s  += __shfl_xor_sync(FULL, s,  k, 16);
        el += __shfl_xor_sync(FULL, el, k, 16);
    }
    float logZ = mx + __logf(s);
    float ent  = logZ - el / s;
    size_t idx = (size_t)tout * B_ + b;
    int a = action[idx];
    float lpa = __shfl_sync(FULL, l, a, 16) - logZ;
    if (lane == 0) {
        out_act[idx] = (float)a;
        out_lp[idx]  = lpa;
        out_ent[idx] = ent;
    }
}

// ---------------- LSTM recurrence + head, 2 batch elems per warp (single wave) ----------------
__global__ __launch_bounds__(128)
void lstm_head(const __nv_bfloat16* __restrict__ A,   // [T,B,128] bf16 gate preacts
               const int*   __restrict__ done,
               const int*   __restrict__ action,
               const float* __restrict__ Whh,          // [128,32]
               const float* __restrict__ Wlog,         // [16,32]
               const float* __restrict__ blog,         // [16]
               const float* __restrict__ h0,
               const float* __restrict__ c0,
               float* __restrict__ out)                // [3,T,B]
{
    __shared__ float WlogT[32][32];
    const int tid = threadIdx.x;
    for (int idx = tid; idx < 1024; idx += 128) {
        int j = idx >> 5, a = idx & 31;
        WlogT[j][a] = (a < 16) ? Wlog[a * 32 + j] : 0.f;
    }
    __syncthreads();

    const int lane = tid & 31;
    const int warp = (blockIdx.x * 128 + tid) >> 5;   // 0..1023
    const int b0 = warp * 2;
    const int b1 = b0 + 1;

    float wi[32], wf[32], wg[32], wo[32];
    #pragma unroll
    for (int j = 0; j < 32; j++) {
        wi[j] = Whh[(     lane) * 32 + j];
        wf[j] = Whh[(32 + lane) * 32 + j];
        wg[j] = Whh[(64 + lane) * 32 + j];
        wo[j] = Whh[(96 + lane) * 32 + j];
    }
    float blogv = (lane < 16) ? blog[lane] : 0.f;

    float hr0 = h0[b0 * 32 + lane], cr0 = c0[b0 * 32 + lane];
    float hr1 = h0[b1 * 32 + lane], cr1 = c0[b1 * 32 + lane];

    float* out_act = out;
    float* out_lp  = out + (size_t)TB_;
    float* out_ent = out + (size_t)2 * TB_;

    const unsigned FULL = 0xffffffffu;

    for (int t = 0; t < T_; t++) {
        const float m0 = 1.f - (float)done[t * B_ + b0];
        const float m1 = 1.f - (float)done[t * B_ + b1];
        const __nv_bfloat16* A0 = A + ((size_t)t * B_ + b0) * 128;
        const __nv_bfloat16* A1 = A0 + 128;
        const float ai0 = __bfloat162float(A0[lane]);
        const float af0 = __bfloat162float(A0[32 + lane]);
        const float ag0 = __bfloat162float(A0[64 + lane]);
        const float ao0 = __bfloat162float(A0[96 + lane]);
        const float ai1 = __bfloat162float(A1[lane]);
        const float af1 = __bfloat162float(A1[32 + lane]);
        const float ag1 = __bfloat162float(A1[64 + lane]);
        const float ao1 = __bfloat162float(A1[96 + lane]);

        float gi0 = 0, gf0 = 0, gg0 = 0, go0 = 0, lp0 = 0;
        float gi1 = 0, gf1 = 0, gg1 = 0, go1 = 0, lp1 = 0;
        #pragma unroll
        for (int j = 0; j < 32; j++) {
            const float hv0 = __shfl_sync(FULL, hr0, j);
            const float hv1 = __shfl_sync(FULL, hr1, j);
            const float wl  = WlogT[j][lane];
            gi0 = fmaf(hv0, wi[j], gi0);  gi1 = fmaf(hv1, wi[j], gi1);
            gf0 = fmaf(hv0, wf[j], gf0);  gf1 = fmaf(hv1, wf[j], gf1);
            gg0 = fmaf(hv0, wg[j], gg0);  gg1 = fmaf(hv1, wg[j], gg1);
            go0 = fmaf(hv0, wo[j], go0);  go1 = fmaf(hv1, wo[j], go1);
            lp0 = fmaf(hv0, wl,    lp0);  lp1 = fmaf(hv1, wl,    lp1);
        }

        if (t > 0) {
            emit_out(t - 1, b0, lane, lp0, blogv, action, out_act, out_lp, out_ent);
            emit_out(t - 1, b1, lane, lp1, blogv, action, out_act, out_lp, out_ent);
        }

        float ig = fast_sig (fmaf(m0, gi0, ai0));
        float fg = fast_sig (fmaf(m0, gf0, af0));
        float gv = fast_tanh(fmaf(m0, gg0, ag0));
        float og = fast_sig (fmaf(m0, go0, ao0));
        cr0 = fg * (m0 * cr0) + ig * gv;
        hr0 = og * fast_tanh(cr0);

        ig = fast_sig (fmaf(m1, gi1, ai1));
        fg = fast_sig (fmaf(m1, gf1, af1));
        gv = fast_tanh(fmaf(m1, gg1, ag1));
        og = fast_sig (fmaf(m1, go1, ao1));
        cr1 = fg * (m1 * cr1) + ig * gv;
        hr1 = og * fast_tanh(cr1);
    }

    float lp0 = 0, lp1 = 0;
    #pragma unroll
    for (int j = 0; j < 32; j++) {
        const float hv0 = __shfl_sync(FULL, hr0, j);
        const float hv1 = __shfl_sync(FULL, hr1, j);
        const float wl  = WlogT[j][lane];
        lp0 = fmaf(hv0, wl, lp0);
        lp1 = fmaf(hv1, wl, lp1);
    }
    emit_out(T_ - 1, b0, lane, lp0, blogv, action, out_act, out_lp, out_ent);
    emit_out(T_ - 1, b1, lane, lp1, blogv, action, out_act, out_lp, out_ent);
}

// ---------------- launcher ----------------
extern "C" void kernel_launch(void* const* d_in, const int* in_sizes, int n_in,
                              void* d_out, int out_size)
{
    (void)in_sizes; (void)n_in; (void)out_size;
    const float* x     = (const float*)d_in[0];
    const int*   done  = (const int*)  d_in[1];
    const int*   action= (const int*)  d_in[2];
    const float* W1    = (const float*)d_in[3];
    const float* b1    = (const float*)d_in[4];
    const float* W2    = (const float*)d_in[5];
    const float* b2    = (const float*)d_in[6];
    const float* W3    = (const float*)d_in[7];
    const float* b3    = (const float*)d_in[8];
    const float* Wih   = (const float*)d_in[9];
    const float* Whh   = (const float*)d_in[10];
    const float* bih   = (const float*)d_in[11];
    const float* bhh   = (const float*)d_in[12];
    const float* Wlog  = (const float*)d_in[13];
    const float* blog  = (const float*)d_in[14];
    const float* h0    = (const float*)d_in[15];
    const float* c0    = (const float*)d_in[16];
    float* out = (float*)d_out;

    void* pA;
    cudaGetSymbolAddress(&pA, g_Abf);
    const __nv_bfloat16* Abuf = (const __nv_bfloat16*)pA;

    cudaFuncSetAttribute(encoder, cudaFuncAttributeMaxDynamicSharedMemorySize, SMEM_BYTES);

    prep_kernel<<<48, 256>>>(W1, W2, Wih, W3, b3, bih, bhh);
    encoder<<<(int)(TB_ / 128), 256, SMEM_BYTES>>>(x, b1, b2);
    lstm_head<<<B_ / 8, 128>>>(Abuf, done, action, Whh, Wlog, blog, h0, c0, out);  // 2 elems/warp, 1 wave
}